// round 3
// baseline (speedup 1.0000x reference)
#include <cuda_runtime.h>
#include <cuda_fp16.h>
#include <cstdint>

#define N_NODES 20000
#define KN      32
#define CIN     512
#define COUT    512
#define KTOT    1024            // concatenated K = [x | agg]

#define BM      32              // rows per CTA (20000 = 625 * 32, exact)
#define BNCH    128             // output-column chunk
#define NCHUNKS (COUT / BNCH)   // 4
#define BK      64              // halves of K per B stage
#define NKT     (KTOT / BK)     // 16

#define AH      1032            // A row stride in halves
#define BH      72              // B row stride in halves

// fp16 weight cache [n][k] with k = concat(Wl, Wr); + pre-summed bias
__device__ __half g_Wh[(size_t)COUT * KTOT];
__device__ float  g_bias[COUT];

// ---------------------------------------------------------------------------
// Kernel 0: convert W -> fp16 concat layout, and bias sum (tiny)
// ---------------------------------------------------------------------------
__global__ void __launch_bounds__(256) convert_kernel(
    const float* __restrict__ Wl, const float* __restrict__ bl,
    const float* __restrict__ Wr, const float* __restrict__ br)
{
    const int n = blockIdx.x;        // 0..511
    const int t = threadIdx.x;       // 0..255
    const int k = t * 4;             // 4 halves per thread, no Wl/Wr straddle
    const float* src = (k < CIN) ? (Wl + (size_t)n * CIN + k)
                                 : (Wr + (size_t)n * CIN + (k - CIN));
    float4 v = *reinterpret_cast<const float4*>(src);
    __half2 h0 = __floats2half2_rn(v.x, v.y);
    __half2 h1 = __floats2half2_rn(v.z, v.w);
    __half2* dst = reinterpret_cast<__half2*>(&g_Wh[(size_t)n * KTOT + k]);
    dst[0] = h0; dst[1] = h1;
    if (n == 0) {
        for (int c = t; c < COUT; c += 256) g_bias[c] = bl[c] + br[c];
    }
}

// ---------------------------------------------------------------------------
// Fused kernel helpers
// ---------------------------------------------------------------------------
__device__ __forceinline__ void cp_async16(void* s, const void* g) {
    uint32_t sa = (uint32_t)__cvta_generic_to_shared(s);
    asm volatile("cp.async.cg.shared.global [%0], [%1], 16;" :: "r"(sa), "l"(g));
}
__device__ __forceinline__ void cp_commit() {
    asm volatile("cp.async.commit_group;");
}
template <int NW>
__device__ __forceinline__ void cp_wait() {
    asm volatile("cp.async.wait_group %0;" :: "n"(NW));
}

__device__ __forceinline__ void mma_f16(float c[4], const uint32_t a[4],
                                        uint32_t b0, uint32_t b1) {
    asm volatile(
        "mma.sync.aligned.m16n8k16.row.col.f32.f16.f16.f32 "
        "{%0,%1,%2,%3}, {%4,%5,%6,%7}, {%8,%9}, {%0,%1,%2,%3};\n"
        : "+f"(c[0]), "+f"(c[1]), "+f"(c[2]), "+f"(c[3])
        : "r"(a[0]), "r"(a[1]), "r"(a[2]), "r"(a[3]), "r"(b0), "r"(b1));
}

// ---------------------------------------------------------------------------
// Fused kernel: per-CTA aggregate + fp16 concat-GEMM with full-K A smem cache
// ---------------------------------------------------------------------------
__global__ void __launch_bounds__(256, 2) fused_kernel(
    const float* __restrict__ x,
    const float* __restrict__ neigh,
    float* __restrict__ out)
{
    extern __shared__ __half sm[];
    __half* Ahs = sm;                       // [BM][AH]
    __half* Bs  = sm + BM * AH;             // [2][BNCH][BH]

    const int tid = threadIdx.x;
    const int m0  = blockIdx.x * BM;

    // ---------- Phase 1a: x rows -> fp16 A-cache (cols 0..511) ----------
#pragma unroll
    for (int i = 0; i < 16; i++) {
        const int idx = tid + i * 256;          // 0..4095
        const int r   = idx >> 7;               // 0..31
        const int c4  = idx & 127;              // float4 index 0..127
        float4 v = __ldg(reinterpret_cast<const float4*>(x)
                         + (size_t)(m0 + r) * (CIN / 4) + c4);
        __half2 h0 = __floats2half2_rn(v.x, v.y);
        __half2 h1 = __floats2half2_rn(v.z, v.w);
        __half2* dst = reinterpret_cast<__half2*>(&Ahs[r * AH + c4 * 4]);
        dst[0] = h0; dst[1] = h1;
    }

    // ---------- Phase 1b: mean(neigh) -> fp16 A-cache (cols 512..1023) ----------
#pragma unroll
    for (int i = 0; i < 16; i++) {
        const int idx = tid + i * 256;
        const int r   = idx >> 7;
        const int c4  = idx & 127;
        const float4* base = reinterpret_cast<const float4*>(neigh)
                             + (size_t)(m0 + r) * KN * (CIN / 4) + c4;
        float sx = 0.f, sy = 0.f, sz = 0.f, sw = 0.f;
#pragma unroll 8
        for (int k = 0; k < KN; k++) {
            float4 v = __ldg(base + (size_t)k * (CIN / 4));
            sx += v.x; sy += v.y; sz += v.z; sw += v.w;
        }
        const float inv = 1.0f / (float)KN;
        __half2 h0 = __floats2half2_rn(sx * inv, sy * inv);
        __half2 h1 = __floats2half2_rn(sz * inv, sw * inv);
        __half2* dst = reinterpret_cast<__half2*>(&Ahs[r * AH + CIN + c4 * 4]);
        dst[0] = h0; dst[1] = h1;
    }
    __syncthreads();

    // ---------- Phase 2: GEMM over 4 n-chunks, B double-buffered ----------
    const int warp = tid >> 5;              // 0..7 -> 16 output cols each
    const int lane = tid & 31;
    const int g    = lane >> 2;             // 0..7
    const int t    = lane & 3;              // 0..3

    // B stage = 128 rows x BK(=64) halves = 128 rows x 8 sixteen-byte segs
    auto issue_b = [&](int kt, int buf, int n0) {
#pragma unroll
        for (int i = 0; i < 4; i++) {
            const int idx = tid + i * 256;      // 0..1023
            const int r   = idx >> 3;           // 0..127
            const int seg = idx & 7;            // 0..7 (16B segments)
            cp_async16(Bs + (size_t)buf * BNCH * BH + r * BH + seg * 8,
                       g_Wh + (size_t)(n0 + r) * KTOT + kt * BK + seg * 8);
        }
        cp_commit();
    };

#pragma unroll 1
    for (int nch = 0; nch < NCHUNKS; nch++) {
        const int n0 = nch * BNCH;

        float acc[2][2][4];
#pragma unroll
        for (int mt = 0; mt < 2; mt++)
#pragma unroll
            for (int nt = 0; nt < 2; nt++)
#pragma unroll
                for (int q = 0; q < 4; q++) acc[mt][nt][q] = 0.f;

        issue_b(0, 0, n0);

#pragma unroll 1
        for (int kt = 0; kt < NKT; kt++) {
            const int cur = kt & 1;
            if (kt + 1 < NKT) { issue_b(kt + 1, cur ^ 1, n0); cp_wait<1>(); }
            else              { cp_wait<0>(); }
            __syncthreads();

            const __half* Bt = Bs + (size_t)cur * BNCH * BH;
#pragma unroll
            for (int ks = 0; ks < 4; ks++) {
                const int kg = kt * BK + ks * 16;   // global k into A cache
                const int kl = ks * 16;             // local k into B tile
                uint32_t a[2][4];
#pragma unroll
                for (int mt = 0; mt < 2; mt++) {
                    const int r0 = mt * 16 + g;
                    a[mt][0] = *reinterpret_cast<const uint32_t*>(&Ahs[r0 * AH + kg + 2 * t]);
                    a[mt][1] = *reinterpret_cast<const uint32_t*>(&Ahs[(r0 + 8) * AH + kg + 2 * t]);
                    a[mt][2] = *reinterpret_cast<const uint32_t*>(&Ahs[r0 * AH + kg + 8 + 2 * t]);
                    a[mt][3] = *reinterpret_cast<const uint32_t*>(&Ahs[(r0 + 8) * AH + kg + 8 + 2 * t]);
                }
#pragma unroll
                for (int nt = 0; nt < 2; nt++) {
                    const int rb = warp * 16 + nt * 8 + g;
                    uint32_t b0 = *reinterpret_cast<const uint32_t*>(&Bt[rb * BH + kl + 2 * t]);
                    uint32_t b1 = *reinterpret_cast<const uint32_t*>(&Bt[rb * BH + kl + 8 + 2 * t]);
#pragma unroll
                    for (int mt = 0; mt < 2; mt++)
                        mma_f16(acc[mt][nt], a[mt], b0, b1);
                }
            }
            __syncthreads();
        }

        // ---------- epilogue for this n-chunk ----------
#pragma unroll
        for (int mt = 0; mt < 2; mt++) {
#pragma unroll
            for (int nt = 0; nt < 2; nt++) {
                const int col  = n0 + warp * 16 + nt * 8 + 2 * t;
                const int row  = m0 + mt * 16 + g;
                const float b0v = g_bias[col];
                const float b1v = g_bias[col + 1];
                float2 v0 = make_float2(acc[mt][nt][0] + b0v, acc[mt][nt][1] + b1v);
                float2 v1 = make_float2(acc[mt][nt][2] + b0v, acc[mt][nt][3] + b1v);
                *reinterpret_cast<float2*>(&out[(size_t)row * COUT + col]) = v0;
                *reinterpret_cast<float2*>(&out[(size_t)(row + 8) * COUT + col]) = v1;
            }
        }
    }
}

// ---------------------------------------------------------------------------
extern "C" void kernel_launch(void* const* d_in, const int* in_sizes, int n_in,
                              void* d_out, int out_size) {
    const float* x  = (const float*)d_in[0];
    const float* nx = (const float*)d_in[1];
    const float* Wl = (const float*)d_in[2];
    const float* bl = (const float*)d_in[3];
    const float* Wr = (const float*)d_in[4];
    const float* br = (const float*)d_in[5];
    float* out = (float*)d_out;

    convert_kernel<<<COUT, 256>>>(Wl, bl, Wr, br);

    const int smem_bytes = (BM * AH + 2 * BNCH * BH) * (int)sizeof(__half); // 102912
    cudaFuncSetAttribute(fused_kernel,
                         cudaFuncAttributeMaxDynamicSharedMemorySize, smem_bytes);
    fused_kernel<<<N_NODES / BM, 256, smem_bytes>>>(x, nx, out);
}

// round 4
// speedup vs baseline: 1.1427x; 1.1427x over previous
#include <cuda_runtime.h>
#include <cuda_fp16.h>
#include <cstdint>

#define N_NODES  20000
#define KN       32
#define CIN      512
#define COUT     512
#define KTOT     1024

#define BM       32
#define NSTRIPES (N_NODES / BM)      // 625
#define NCTA     148

#define AH       1032                // A row stride (halves); 2064B, %128=16 -> ldmatrix conflict-free
#define ABUF_H   (BM * AH)           // 33024 halves per A buffer
#define BH       40                  // B row stride (halves); 80B, %128=16 -> conflict-free
#define BSTAGE_H (COUT * BH)         // 20480 halves per B stage
#define NKT      32                  // K stages of 32 halves each

__device__ __half g_Wh[(size_t)COUT * KTOT];
__device__ float  g_bias[COUT];

// ---------------------------------------------------------------------------
// Kernel 0: W -> fp16 concat layout, bias sum
// ---------------------------------------------------------------------------
__global__ void __launch_bounds__(256) convert_kernel(
    const float* __restrict__ Wl, const float* __restrict__ bl,
    const float* __restrict__ Wr, const float* __restrict__ br)
{
    const int n = blockIdx.x;
    const int t = threadIdx.x;
    const int k = t * 4;
    const float* src = (k < CIN) ? (Wl + (size_t)n * CIN + k)
                                 : (Wr + (size_t)n * CIN + (k - CIN));
    float4 v = *reinterpret_cast<const float4*>(src);
    __half2* dst = reinterpret_cast<__half2*>(&g_Wh[(size_t)n * KTOT + k]);
    dst[0] = __floats2half2_rn(v.x, v.y);
    dst[1] = __floats2half2_rn(v.z, v.w);
    if (n == 0)
        for (int c = t; c < COUT; c += 256) g_bias[c] = bl[c] + br[c];
}

// ---------------------------------------------------------------------------
// PTX helpers
// ---------------------------------------------------------------------------
__device__ __forceinline__ void cp_async16_s(uint32_t saddr, const void* g) {
    asm volatile("cp.async.cg.shared.global [%0], [%1], 16;" :: "r"(saddr), "l"(g));
}
__device__ __forceinline__ void cp_commit() {
    asm volatile("cp.async.commit_group;");
}
template <int NW>
__device__ __forceinline__ void cp_wait() {
    asm volatile("cp.async.wait_group %0;" :: "n"(NW));
}
__device__ __forceinline__ void ldsm_x4(uint32_t r[4], uint32_t saddr) {
    asm volatile("ldmatrix.sync.aligned.m8n8.x4.shared.b16 {%0,%1,%2,%3}, [%4];"
                 : "=r"(r[0]), "=r"(r[1]), "=r"(r[2]), "=r"(r[3]) : "r"(saddr));
}
__device__ __forceinline__ void mma_f16(float c[4], const uint32_t a[4],
                                        uint32_t b0, uint32_t b1) {
    asm volatile(
        "mma.sync.aligned.m16n8k16.row.col.f32.f16.f16.f32 "
        "{%0,%1,%2,%3}, {%4,%5,%6,%7}, {%8,%9}, {%0,%1,%2,%3};\n"
        : "+f"(c[0]), "+f"(c[1]), "+f"(c[2]), "+f"(c[3])
        : "r"(a[0]), "r"(a[1]), "r"(a[2]), "r"(a[3]), "r"(b0), "r"(b1));
}

// ---------------------------------------------------------------------------
// Aggregation fill: stripe rows [row0, row0+32) -> fp16 A-cache [32][AH]
// cols 0..511 = x, cols 512..1023 = mean(neigh)
// ---------------------------------------------------------------------------
template <int NT>
__device__ __forceinline__ void fill_A(const float* __restrict__ x,
                                       const float* __restrict__ neigh,
                                       int row0, __half* Adst, int t)
{
#pragma unroll
    for (int i = 0; i < 4096 / NT; i++) {
        const int idx = t + i * NT;
        const int r   = idx >> 7;
        const int c4  = idx & 127;
        float4 v = __ldg(reinterpret_cast<const float4*>(x)
                         + (size_t)(row0 + r) * (CIN / 4) + c4);
        __half2* dst = reinterpret_cast<__half2*>(Adst + r * AH + c4 * 4);
        dst[0] = __floats2half2_rn(v.x, v.y);
        dst[1] = __floats2half2_rn(v.z, v.w);
    }
#pragma unroll
    for (int i = 0; i < 4096 / NT; i++) {
        const int idx = t + i * NT;
        const int r   = idx >> 7;
        const int c4  = idx & 127;
        const float4* base = reinterpret_cast<const float4*>(neigh)
                             + (size_t)(row0 + r) * KN * (CIN / 4) + c4;
        float sx = 0.f, sy = 0.f, sz = 0.f, sw = 0.f;
#pragma unroll 8
        for (int k = 0; k < KN; k++) {
            float4 v = __ldg(base + (size_t)k * (CIN / 4));
            sx += v.x; sy += v.y; sz += v.z; sw += v.w;
        }
        const float inv = 1.0f / (float)KN;
        __half2* dst = reinterpret_cast<__half2*>(Adst + r * AH + CIN + c4 * 4);
        dst[0] = __floats2half2_rn(sx * inv, sy * inv);
        dst[1] = __floats2half2_rn(sz * inv, sw * inv);
    }
}

// ---------------------------------------------------------------------------
// Persistent warp-specialized kernel
// ---------------------------------------------------------------------------
__global__ void __launch_bounds__(512, 1) fused_kernel(
    const float* __restrict__ x,
    const float* __restrict__ neigh,
    float* __restrict__ out)
{
    extern __shared__ __half sm[];
    __half* Abuf = sm;                      // [2][BM][AH]
    __half* Bbuf = sm + 2 * ABUF_H;         // [2][COUT][BH]

    const int tid  = threadIdx.x;
    const int lane = tid & 31;
    const int w    = tid >> 5;              // consumer warp id when tid<256
    const int s0   = blockIdx.x;

    // prologue: everyone fills stripe s0 into buffer 0
    fill_A<512>(x, neigh, s0 * BM, Abuf, tid);

    // consumer-only persistent state
    float bias0[8], bias1[8];
    uint32_t Abase = 0, Bbase = 0, a_lane = 0, b_lane = 0;
    int g = lane >> 2, t4 = lane & 3;
    if (tid < 256) {
#pragma unroll
        for (int nt = 0; nt < 8; nt++) {
            const int col = w * 64 + nt * 8 + 2 * t4;
            bias0[nt] = g_bias[col];
            bias1[nt] = g_bias[col + 1];
        }
        Abase = (uint32_t)__cvta_generic_to_shared(Abuf);
        Bbase = (uint32_t)__cvta_generic_to_shared(Bbuf);
        // A ldmatrix lane addr: row (lane&15), k-half (lane>>4)*8
        a_lane = (uint32_t)(((lane & 15) * AH + (lane >> 4) * 8) * 2);
        // B ldmatrix lane addr: row w*64 + (lane>>4)*8 + (lane&7), k-half ((lane>>3)&1)*8
        b_lane = (uint32_t)(((w * 64 + ((lane >> 4) << 3) + (lane & 7)) * BH
                             + ((lane >> 3) & 1) * 8) * 2);
    }
    __syncthreads();

    int buf = 0;
#pragma unroll 1
    for (int s = s0; s < NSTRIPES; s += NCTA) {
        if (tid < 256) {
            // ======== consumer: GEMM stripe s, cols w*64..w*64+63 ========
            const uint32_t Ab = Abase + (uint32_t)(buf * ABUF_H * 2);

            float acc[2][8][4];
#pragma unroll
            for (int mt = 0; mt < 2; mt++)
#pragma unroll
                for (int nt = 0; nt < 8; nt++)
#pragma unroll
                    for (int q = 0; q < 4; q++) acc[mt][nt][q] = 0.f;

            // per-warp-private B stage loader (64 rows x 64B)
            auto issueB = [&](int kt) {
                const uint32_t dpar = (uint32_t)((kt & 1) * BSTAGE_H * 2);
#pragma unroll
                for (int i = 0; i < 8; i++) {
                    const int idx = lane + i * 32;
                    const int r   = w * 64 + (idx >> 2);
                    const int seg = idx & 3;
                    cp_async16_s(Bbase + dpar + (uint32_t)((r * BH + seg * 8) * 2),
                                 g_Wh + (size_t)r * KTOT + kt * 32 + seg * 8);
                }
                cp_commit();
            };

            issueB(0);
#pragma unroll 1
            for (int kt = 0; kt < NKT; kt++) {
                if (kt + 1 < NKT) { issueB(kt + 1); cp_wait<1>(); }
                else              { cp_wait<0>(); }

                const uint32_t apar = Ab + a_lane + (uint32_t)(kt * 64);
                const uint32_t bpar = Bbase + (uint32_t)((kt & 1) * BSTAGE_H * 2) + b_lane;
#pragma unroll
                for (int ks = 0; ks < 2; ks++) {
                    uint32_t a0[4], a1[4];
                    ldsm_x4(a0, apar + ks * 32);
                    ldsm_x4(a1, apar + ks * 32 + 16 * AH * 2);
#pragma unroll
                    for (int p = 0; p < 4; p++) {
                        uint32_t b[4];
                        ldsm_x4(b, bpar + ks * 32 + p * (16 * BH * 2));
                        mma_f16(acc[0][2 * p],     a0, b[0], b[1]);
                        mma_f16(acc[1][2 * p],     a1, b[0], b[1]);
                        mma_f16(acc[0][2 * p + 1], a0, b[2], b[3]);
                        mma_f16(acc[1][2 * p + 1], a1, b[2], b[3]);
                    }
                }
            }

            // epilogue
            const int m0 = s * BM;
#pragma unroll
            for (int mt = 0; mt < 2; mt++)
#pragma unroll
                for (int nt = 0; nt < 8; nt++) {
                    const int col = w * 64 + nt * 8 + 2 * t4;
                    const int row = m0 + mt * 16 + g;
                    *reinterpret_cast<float2*>(&out[(size_t)row * COUT + col]) =
                        make_float2(acc[mt][nt][0] + bias0[nt], acc[mt][nt][1] + bias1[nt]);
                    *reinterpret_cast<float2*>(&out[(size_t)(row + 8) * COUT + col]) =
                        make_float2(acc[mt][nt][2] + bias0[nt], acc[mt][nt][3] + bias1[nt]);
                }
        } else {
            // ======== producer: aggregate stripe s+NCTA into other buffer ========
            const int sn = s + NCTA;
            if (sn < NSTRIPES)
                fill_A<256>(x, neigh, sn * BM, Abuf + (buf ^ 1) * ABUF_H, tid - 256);
        }
        __syncthreads();
        buf ^= 1;
    }
}

// ---------------------------------------------------------------------------
extern "C" void kernel_launch(void* const* d_in, const int* in_sizes, int n_in,
                              void* d_out, int out_size) {
    const float* x  = (const float*)d_in[0];
    const float* nx = (const float*)d_in[1];
    const float* Wl = (const float*)d_in[2];
    const float* bl = (const float*)d_in[3];
    const float* Wr = (const float*)d_in[4];
    const float* br = (const float*)d_in[5];
    float* out = (float*)d_out;

    convert_kernel<<<COUT, 256>>>(Wl, bl, Wr, br);

    const int smem_bytes = (2 * ABUF_H + 2 * BSTAGE_H) * (int)sizeof(__half); // 214016
    cudaFuncSetAttribute(fused_kernel,
                         cudaFuncAttributeMaxDynamicSharedMemorySize, smem_bytes);
    fused_kernel<<<NCTA, 512, smem_bytes>>>(x, nx, out);
}